// round 16
// baseline (speedup 1.0000x reference)
#include <cuda_runtime.h>
#include <cuda_fp16.h>
#include <cstdint>

#define NUM_EMB 41025
#define BATCH   16384
#define BAG     30
#define BAGP    32         // padded bag (pad index = 0 -> zero row)
#define P       8          // positions per block (1 warp each)
#define NT      256
#define GRID    (BATCH / P)

#define ROW_U4  32                     // 256 halves = 32 uint4 per row
#define ROW_B   512
#define TBL_U4  (NUM_EMB * ROW_U4)

// TMA ring: per warp 2 buffers x 8 rows x 512 B = 8192 B
#define TCHUNK_B 4096

// dynamic smem layout (bytes)
#define OFF_TMA  0
#define SZ_TMA   (P * 2 * TCHUNK_B)              // 65536
#define OFF_IDX  (OFF_TMA + SZ_TMA)              // 65536
#define SZ_IDX   (P * 2 * BAGP * 4)              // 2048
#define OFF_XH   (OFF_IDX + SZ_IDX)              // 67584
#define SZ_XH    (P * 256 * 4)                   // 8192
#define OFF_H1   (OFF_XH + SZ_XH)                // 75776
#define SZ_H1    (P * 32 * 4)                    // 1024
#define OFF_MBAR (OFF_H1 + SZ_H1)                // 76800
#define SZ_MBAR  (P * 2 * 8)                     // 128
#define SMEM_TOTAL (OFF_MBAR + SZ_MBAR)          // 76928

// fp16 shadow tables (scratch): [0]=white, [1]=black. 21 MB each.
__device__ uint4 g_ft16[2][TBL_U4];

// ---- packed f32x2 helpers ----
__device__ __forceinline__ void add_f32x2(uint64_t& acc, uint64_t v) {
    asm("add.rn.f32x2 %0, %1, %2;" : "=l"(acc) : "l"(acc), "l"(v));
}
__device__ __forceinline__ void fma_f32x2(uint64_t& acc, uint64_t a, uint64_t b) {
    asm("fma.rn.f32x2 %0, %1, %2, %3;" : "=l"(acc) : "l"(a), "l"(b), "l"(acc));
}
__device__ __forceinline__ uint64_t h2_to_f32x2(__half2 h) {
    float2 f = __half22float2(h);
    uint64_t r;
    asm("mov.b64 %0, {%1, %2};" : "=l"(r) : "f"(f.x), "f"(f.y));
    return r;
}
__device__ __forceinline__ float2 unpack_f32x2(uint64_t v) {
    float2 f;
    asm("mov.b64 {%0, %1}, %2;" : "=f"(f.x), "=f"(f.y) : "l"(v));
    return f;
}
__device__ __forceinline__ uint64_t pack_f32x2(float x, float y) {
    uint64_t r;
    asm("mov.b64 %0, {%1, %2};" : "=l"(r) : "f"(x), "f"(y));
    return r;
}

// ---- mbarrier / bulk-copy helpers ----
__device__ __forceinline__ void mbar_init(uint32_t addr, uint32_t count) {
    asm volatile("mbarrier.init.shared.b64 [%0], %1;" :: "r"(addr), "r"(count) : "memory");
}
__device__ __forceinline__ void mbar_expect_tx(uint32_t addr, uint32_t bytes) {
    asm volatile("mbarrier.arrive.expect_tx.shared.b64 _, [%0], %1;"
                 :: "r"(addr), "r"(bytes) : "memory");
}
__device__ __forceinline__ void mbar_wait(uint32_t addr, uint32_t phase) {
    asm volatile(
        "{\n\t.reg .pred P;\n"
        "W%=:\n\t"
        "mbarrier.try_wait.parity.acquire.cta.shared::cta.b64 P, [%0], %1;\n\t"
        "@P bra D%=;\n\t"
        "bra W%=;\n"
        "D%=:\n\t}"
        :: "r"(addr), "r"(phase) : "memory");
}
__device__ __forceinline__ void bulk_copy_g2s(uint32_t dst, const void* src,
                                              uint32_t bytes, uint32_t mbar) {
    asm volatile(
        "cp.async.bulk.shared::cluster.global.mbarrier::complete_tx::bytes "
        "[%0], [%1], %2, [%3];"
        :: "r"(dst), "l"(src), "r"(bytes), "r"(mbar) : "memory");
}

// ---------------------------------------------------------------------------
// Pre-pass: convert both f32 tables to fp16.
// ---------------------------------------------------------------------------
__global__ __launch_bounds__(256)
void cvt_kernel(const float4* __restrict__ ftw, const float4* __restrict__ ftb)
{
    const int i = blockIdx.x * blockDim.x + threadIdx.x;
    if (i >= 2 * TBL_U4) return;
    const int tbl = (i >= TBL_U4);
    const int j   = tbl ? (i - TBL_U4) : i;
    const float4* src = tbl ? ftb : ftw;

    const float4 a = __ldcs(&src[2 * j]);
    const float4 b = __ldcs(&src[2 * j + 1]);

    __half2 h0 = __floats2half2_rn(a.x, a.y);
    __half2 h1 = __floats2half2_rn(a.z, a.w);
    __half2 h2 = __floats2half2_rn(b.x, b.y);
    __half2 h3 = __floats2half2_rn(b.z, b.w);

    uint4 o;
    o.x = *reinterpret_cast<unsigned*>(&h0);
    o.y = *reinterpret_cast<unsigned*>(&h1);
    o.z = *reinterpret_cast<unsigned*>(&h2);
    o.w = *reinterpret_cast<unsigned*>(&h3);
    __stcg(&g_ft16[tbl][j], o);
}

// ---------------------------------------------------------------------------
// Main kernel: hybrid gather. White table via LDG double-buffer (l1tex path),
// black table via cp.async.bulk 2-stage smem ring (TMA path). The two memory
// engines run concurrently.
// ---------------------------------------------------------------------------
__global__ __launch_bounds__(NT, 2)
void nnue_kernel(const int* __restrict__ wi,
                 const int* __restrict__ bi,
                 const float4* __restrict__ fc1w,   // [32][128] float4
                 const float* __restrict__ fc1b,
                 const float4* __restrict__ fc2w,   // [32][8] float4
                 const float* __restrict__ fc2b,
                 const float* __restrict__ fc3w,
                 const float* __restrict__ fc3b,
                 float* __restrict__ out)
{
    extern __shared__ __align__(1024) char dsm[];
    int*     s_idx = reinterpret_cast<int*>(dsm + OFF_IDX);     // [P][2][BAGP]
    __half2* s_xh  = reinterpret_cast<__half2*>(dsm + OFF_XH);  // [P][256]
    float*   s_h1  = reinterpret_cast<float*>(dsm + OFF_H1);    // [P][32]

    const int tid  = threadIdx.x;
    const int lane = tid & 31;
    const int warp = tid >> 5;
    const int p0   = blockIdx.x * P;

    const uint32_t smem_u32 = (uint32_t)__cvta_generic_to_shared(dsm);
    const uint32_t tma_w    = smem_u32 + OFF_TMA + warp * (2 * TCHUNK_B);
    const uint32_t mbar_w   = smem_u32 + OFF_MBAR + warp * 16;

    // ---- per-warp mbarrier init + index staging ----
    if (lane == 0) {
        mbar_init(mbar_w, 1);
        mbar_init(mbar_w + 8, 1);
        asm volatile("fence.proxy.async.shared::cta;" ::: "memory");
    }
    {
        const int pos = p0 + warp;
        int vw = 0, vb = 0;
        if (lane < BAG) {
            vw = __ldg(&wi[pos * BAG + lane]);
            vb = __ldg(&bi[pos * BAG + lane]);
        }
        s_idx[(warp * 2 + 0) * BAGP + lane] = vw;   // pad lanes write 0
        s_idx[(warp * 2 + 1) * BAGP + lane] = vb;
    }
    __syncwarp();

    // ---- hybrid gather ----
    {
        uint64_t accW[4], accB[4];
#pragma unroll
        for (int k = 0; k < 4; k++) { accW[k] = 0ull; accB[k] = 0ull; }

        const uint4* tw = g_ft16[0];
        const int4*  iw4   = reinterpret_cast<const int4*>(s_idx + warp * 2 * BAGP);
        const int*   ib    = s_idx + (warp * 2 + 1) * BAGP;

        // TMA issue of black chunk k (8 rows, 4096 B) into buffer k&1.
        auto issue_tma = [&](int k) {
            const uint32_t mb = mbar_w + 8 * (k & 1);
            if (lane == 0)
                mbar_expect_tx(mb, TCHUNK_B);
            __syncwarp();
            if (lane < 8) {
                const int idx = ib[8 * k + lane];
                const char* src = reinterpret_cast<const char*>(g_ft16[1])
                                  + (size_t)idx * ROW_B;
                bulk_copy_g2s(tma_w + (k & 1) * TCHUNK_B + lane * ROW_B,
                              src, ROW_B, mb);
            }
        };

        // white LDG chunk c: rows 4c..4c+3
        uint4 A[4], B[4];
        auto load_w = [&](uint4* buf, int c) {
            const int4 iw = iw4[c];
            buf[0] = __ldcg(&tw[(size_t)iw.x * ROW_U4 + lane]);
            buf[1] = __ldcg(&tw[(size_t)iw.y * ROW_U4 + lane]);
            buf[2] = __ldcg(&tw[(size_t)iw.z * ROW_U4 + lane]);
            buf[3] = __ldcg(&tw[(size_t)iw.w * ROW_U4 + lane]);
        };
        auto consume_w = [&](const uint4* buf) {
            const __half2* r0 = reinterpret_cast<const __half2*>(&buf[0]);
            const __half2* r1 = reinterpret_cast<const __half2*>(&buf[1]);
            const __half2* r2 = reinterpret_cast<const __half2*>(&buf[2]);
            const __half2* r3 = reinterpret_cast<const __half2*>(&buf[3]);
#pragma unroll
            for (int k = 0; k < 4; k++) {
                __half2 hw = __hadd2(__hadd2(r0[k], r1[k]),
                                     __hadd2(r2[k], r3[k]));
                add_f32x2(accW[k], h2_to_f32x2(hw));
            }
        };
        // black consume of iter c: 4 rows from the TMA ring
        auto consume_b = [&](int c) {
            const uint4* brow = reinterpret_cast<const uint4*>(
                dsm + OFF_TMA + warp * (2 * TCHUNK_B)
                + ((c >> 1) & 1) * TCHUNK_B + (c & 1) * 2048);
            const uint4 v0 = brow[lane];
            const uint4 v1 = brow[32 + lane];
            const uint4 v2 = brow[64 + lane];
            const uint4 v3 = brow[96 + lane];
            const __half2* r0 = reinterpret_cast<const __half2*>(&v0);
            const __half2* r1 = reinterpret_cast<const __half2*>(&v1);
            const __half2* r2 = reinterpret_cast<const __half2*>(&v2);
            const __half2* r3 = reinterpret_cast<const __half2*>(&v3);
#pragma unroll
            for (int k = 0; k < 4; k++) {
                __half2 hb = __hadd2(__hadd2(r0[k], r1[k]),
                                     __hadd2(r2[k], r3[k]));
                add_f32x2(accB[k], h2_to_f32x2(hb));
            }
        };

        load_w(A, 0);
        load_w(B, 1);
        issue_tma(0);
        issue_tma(1);

#pragma unroll
        for (int c = 0; c < 8; c++) {
            if ((c & 1) == 0)
                mbar_wait(mbar_w + 8 * ((c >> 1) & 1), (c >> 2) & 1);

            uint4* cur = (c & 1) ? B : A;
            consume_w(cur);
            if (c + 2 < 8)
                load_w(cur, c + 2);

            consume_b(c);

            if ((c & 1) == 1 && (c >> 1) + 2 < 4)
                issue_tma((c >> 1) + 2);
        }

        // relu in f32, convert to fp16, store x: 2 x STS.128 per warp.
        __half2 hW[4], hB[4];
#pragma unroll
        for (int k = 0; k < 4; k++) {
            float2 fw = unpack_f32x2(accW[k]);
            float2 fb = unpack_f32x2(accB[k]);
            hW[k] = __floats2half2_rn(fmaxf(fw.x, 0.f), fmaxf(fw.y, 0.f));
            hB[k] = __floats2half2_rn(fmaxf(fb.x, 0.f), fmaxf(fb.y, 0.f));
        }
        *reinterpret_cast<uint4*>(&s_xh[warp * 256 + 4 * lane]) =
            *reinterpret_cast<uint4*>(hW);
        *reinterpret_cast<uint4*>(&s_xh[warp * 256 + 128 + 4 * lane]) =
            *reinterpret_cast<uint4*>(hB);
    }

    // ---- FC1 weights -> 64 registers (gather buffers dead) ----
    uint64_t wp[4][8];
    float    b1r[4];
#pragma unroll
    for (int oo = 0; oo < 4; oo++) {
        const int o = 4 * warp + oo;
#pragma unroll
        for (int k = 0; k < 4; k++) {
            const float4 w = __ldg(&fc1w[(size_t)o * 128 + lane + 32 * k]);
            wp[oo][2 * k]     = pack_f32x2(w.x, w.y);
            wp[oo][2 * k + 1] = pack_f32x2(w.z, w.w);
        }
        b1r[oo] = __ldg(&fc1b[o]);
    }
    __syncthreads();

    // ---- FC1: warp computes its 4 outputs for all 8 positions ----
#pragma unroll
    for (int pos = 0; pos < P; pos++) {
        uint64_t xp[8];
#pragma unroll
        for (int k = 0; k < 4; k++) {
            const uint2 v = *reinterpret_cast<const uint2*>(
                &s_xh[pos * 256 + 2 * (lane + 32 * k)]);
            const __half2 lo = *reinterpret_cast<const __half2*>(&v.x);
            const __half2 hi = *reinterpret_cast<const __half2*>(&v.y);
            xp[2 * k]     = h2_to_f32x2(lo);
            xp[2 * k + 1] = h2_to_f32x2(hi);
        }
        float part[4];
#pragma unroll
        for (int oo = 0; oo < 4; oo++) {
            uint64_t acc = 0ull;
#pragma unroll
            for (int k = 0; k < 8; k++)
                fma_f32x2(acc, wp[oo][k], xp[k]);
            const float2 f = unpack_f32x2(acc);
            part[oo] = f.x + f.y;
        }
#pragma unroll
        for (int off = 16; off > 0; off >>= 1) {
#pragma unroll
            for (int oo = 0; oo < 4; oo++)
                part[oo] += __shfl_xor_sync(0xffffffffu, part[oo], off);
        }
        if (lane == 0) {
#pragma unroll
            for (int oo = 0; oo < 4; oo++)
                s_h1[pos * 32 + 4 * warp + oo] = fmaxf(part[oo] + b1r[oo], 0.f);
        }
    }
    __syncthreads();

    // ---- FC2 (32->32, relu) + FC3 (32->1): warp w handles position w ----
    {
        const float* h = s_h1 + warp * 32;
        float s = __ldg(&fc2b[lane]);
        const float4* w2 = fc2w + (size_t)lane * 8;
#pragma unroll
        for (int k = 0; k < 8; k++) {
            const float4 w = __ldg(&w2[k]);
            s += w.x * h[4 * k + 0];
            s += w.y * h[4 * k + 1];
            s += w.z * h[4 * k + 2];
            s += w.w * h[4 * k + 3];
        }
        float v = fmaxf(s, 0.f) * __ldg(&fc3w[lane]);
#pragma unroll
        for (int off = 16; off > 0; off >>= 1)
            v += __shfl_xor_sync(0xffffffffu, v, off);
        if (lane == 0)
            out[p0 + warp] = v + __ldg(&fc3b[0]);
    }
}

extern "C" void kernel_launch(void* const* d_in, const int* in_sizes, int n_in,
                              void* d_out, int out_size)
{
    const int*    wiP   = (const int*)d_in[0];
    const int*    biP   = (const int*)d_in[2];
    const float4* ftw   = (const float4*)d_in[4];
    const float4* ftb   = (const float4*)d_in[5];
    const float4* fc1w  = (const float4*)d_in[6];
    const float*  fc1b  = (const float*)d_in[7];
    const float4* fc2w  = (const float4*)d_in[8];
    const float*  fc2b  = (const float*)d_in[9];
    const float*  fc3w  = (const float*)d_in[10];
    const float*  fc3b  = (const float*)d_in[11];
    float* outP = (float*)d_out;

    cudaFuncSetAttribute(nnue_kernel,
                         cudaFuncAttributeMaxDynamicSharedMemorySize,
                         SMEM_TOTAL);

    const int n_cvt = 2 * TBL_U4;
    cvt_kernel<<<(n_cvt + 255) / 256, 256>>>(ftw, ftb);
    nnue_kernel<<<GRID, NT, SMEM_TOTAL>>>(wiP, biP, fc1w, fc1b,
                                          fc2w, fc2b, fc3w, fc3b, outP);
}

// round 17
// speedup vs baseline: 1.0772x; 1.0772x over previous
#include <cuda_runtime.h>
#include <cuda_fp16.h>
#include <cstdint>

#define NUM_EMB 41025
#define BATCH   16384
#define BAG     30
#define BAGP    32         // padded bag (pad index = 0 -> zero row)
#define P       8          // positions per block (1 warp each)
#define NT      256
#define GRID    (BATCH / P)

#define ROW_U4  32                     // 256 halves = 32 uint4 per row
#define TBL_U4  (NUM_EMB * ROW_U4)     // 1,312,800 uint4 per table

// fp16 shadow tables (scratch): [0]=white, [1]=black. 21 MB each.
// 1024B alignment: every 512B row covers exactly 4 cache lines (16 sectors).
__device__ __align__(1024) uint4 g_ft16[2][TBL_U4];

// ---- packed f32x2 helpers (Blackwell sm_103a) ----
__device__ __forceinline__ void add_f32x2(uint64_t& acc, uint64_t v) {
    asm("add.rn.f32x2 %0, %1, %2;" : "=l"(acc) : "l"(acc), "l"(v));
}
__device__ __forceinline__ void fma_f32x2(uint64_t& acc, uint64_t a, uint64_t b) {
    asm("fma.rn.f32x2 %0, %1, %2, %3;" : "=l"(acc) : "l"(a), "l"(b), "l"(acc));
}
__device__ __forceinline__ uint64_t h2_to_f32x2(__half2 h) {
    float2 f = __half22float2(h);
    uint64_t r;
    asm("mov.b64 %0, {%1, %2};" : "=l"(r) : "f"(f.x), "f"(f.y));
    return r;
}
__device__ __forceinline__ float2 unpack_f32x2(uint64_t v) {
    float2 f;
    asm("mov.b64 {%0, %1}, %2;" : "=f"(f.x), "=f"(f.y) : "l"(v));
    return f;
}
__device__ __forceinline__ uint64_t pack_f32x2(float x, float y) {
    uint64_t r;
    asm("mov.b64 %0, {%1, %2};" : "=l"(r) : "f"(x), "f"(y));
    return r;
}

// ---------------------------------------------------------------------------
// Pre-pass: convert both f32 tables to fp16 (streaming reads, L2 writes).
// ---------------------------------------------------------------------------
__global__ __launch_bounds__(256)
void cvt_kernel(const float4* __restrict__ ftw, const float4* __restrict__ ftb)
{
    const int i = blockIdx.x * blockDim.x + threadIdx.x;
    if (i >= 2 * TBL_U4) return;
    const int tbl = (i >= TBL_U4);
    const int j   = tbl ? (i - TBL_U4) : i;
    const float4* src = tbl ? ftb : ftw;

    const float4 a = __ldcs(&src[2 * j]);
    const float4 b = __ldcs(&src[2 * j + 1]);

    __half2 h0 = __floats2half2_rn(a.x, a.y);
    __half2 h1 = __floats2half2_rn(a.z, a.w);
    __half2 h2 = __floats2half2_rn(b.x, b.y);
    __half2 h3 = __floats2half2_rn(b.z, b.w);

    uint4 o;
    o.x = *reinterpret_cast<unsigned*>(&h0);
    o.y = *reinterpret_cast<unsigned*>(&h1);
    o.z = *reinterpret_cast<unsigned*>(&h2);
    o.w = *reinterpret_cast<unsigned*>(&h3);
    __stcg(&g_ft16[tbl][j], o);
}

// ---------------------------------------------------------------------------
// Main kernel. Explicit register double-buffered gather (R15 structure).
// ---------------------------------------------------------------------------
__global__ __launch_bounds__(NT, 2)
void nnue_kernel(const int* __restrict__ wi,
                 const int* __restrict__ bi,
                 const float4* __restrict__ fc1w,   // [32][128] float4
                 const float* __restrict__ fc1b,
                 const float4* __restrict__ fc2w,   // [32][8] float4
                 const float* __restrict__ fc2b,
                 const float* __restrict__ fc3w,
                 const float* __restrict__ fc3b,
                 float* __restrict__ out)
{
    __shared__ __align__(16) int     s_idx[P][2][BAGP];
    __shared__ __align__(16) __half2 s_xh[P][256];   // concat x, fp16
    __shared__ float s_h1[P][32];

    const int tid  = threadIdx.x;
    const int lane = tid & 31;
    const int warp = tid >> 5;
    const int p0   = blockIdx.x * P;

    // ---- per-warp index staging (no block barrier, no div/mod) ----
    {
        const int pos = p0 + warp;
        int vw = 0, vb = 0;
        if (lane < BAG) {
            vw = __ldg(&wi[pos * BAG + lane]);
            vb = __ldg(&bi[pos * BAG + lane]);
        }
        s_idx[warp][0][lane] = vw;      // lanes 30,31 write pad 0
        s_idx[warp][1][lane] = vb;
        __syncwarp();
    }

    // ---- gather: warp w owns position w. Register double-buffered:
    //      8 chunks x (4 white + 4 black) rows; two chunk buffers in flight.
    {
        uint64_t accW[4], accB[4];
#pragma unroll
        for (int k = 0; k < 4; k++) { accW[k] = 0ull; accB[k] = 0ull; }

        const uint4* tw = g_ft16[0];
        const uint4* tb = g_ft16[1];
        const int4* iw4 = reinterpret_cast<const int4*>(s_idx[warp][0]);
        const int4* ib4 = reinterpret_cast<const int4*>(s_idx[warp][1]);

        uint4 A[8], B[8];

        auto load_chunk = [&](uint4* buf, int c) {
            const int4 iw = iw4[c];
            const int4 ib = ib4[c];
            buf[0] = __ldcg(&tw[(size_t)iw.x * ROW_U4 + lane]);
            buf[1] = __ldcg(&tw[(size_t)iw.y * ROW_U4 + lane]);
            buf[2] = __ldcg(&tw[(size_t)iw.z * ROW_U4 + lane]);
            buf[3] = __ldcg(&tw[(size_t)iw.w * ROW_U4 + lane]);
            buf[4] = __ldcg(&tb[(size_t)ib.x * ROW_U4 + lane]);
            buf[5] = __ldcg(&tb[(size_t)ib.y * ROW_U4 + lane]);
            buf[6] = __ldcg(&tb[(size_t)ib.z * ROW_U4 + lane]);
            buf[7] = __ldcg(&tb[(size_t)ib.w * ROW_U4 + lane]);
        };

        auto consume = [&](const uint4* buf) {
            const __half2* r0 = reinterpret_cast<const __half2*>(&buf[0]);
            const __half2* r1 = reinterpret_cast<const __half2*>(&buf[1]);
            const __half2* r2 = reinterpret_cast<const __half2*>(&buf[2]);
            const __half2* r3 = reinterpret_cast<const __half2*>(&buf[3]);
            const __half2* r4 = reinterpret_cast<const __half2*>(&buf[4]);
            const __half2* r5 = reinterpret_cast<const __half2*>(&buf[5]);
            const __half2* r6 = reinterpret_cast<const __half2*>(&buf[6]);
            const __half2* r7 = reinterpret_cast<const __half2*>(&buf[7]);
#pragma unroll
            for (int k = 0; k < 4; k++) {
                __half2 hw = __hadd2(__hadd2(r0[k], r1[k]),
                                     __hadd2(r2[k], r3[k]));
                __half2 hb = __hadd2(__hadd2(r4[k], r5[k]),
                                     __hadd2(r6[k], r7[k]));
                add_f32x2(accW[k], h2_to_f32x2(hw));
                add_f32x2(accB[k], h2_to_f32x2(hb));
            }
        };

        load_chunk(A, 0);
        load_chunk(B, 1);
        consume(A); load_chunk(A, 2);
        consume(B); load_chunk(B, 3);
        consume(A); load_chunk(A, 4);
        consume(B); load_chunk(B, 5);
        consume(A); load_chunk(A, 6);
        consume(B); load_chunk(B, 7);
        consume(A);
        consume(B);

        // relu in f32, convert to fp16, store: 2 x STS.128 per warp.
        __half2 hW[4], hB[4];
#pragma unroll
        for (int k = 0; k < 4; k++) {
            float2 fw = unpack_f32x2(accW[k]);
            float2 fb = unpack_f32x2(accB[k]);
            hW[k] = __floats2half2_rn(fmaxf(fw.x, 0.f), fmaxf(fw.y, 0.f));
            hB[k] = __floats2half2_rn(fmaxf(fb.x, 0.f), fmaxf(fb.y, 0.f));
        }
        *reinterpret_cast<uint4*>(&s_xh[warp][4 * lane]) =
            *reinterpret_cast<uint4*>(hW);          // white cols 8l..8l+7
        *reinterpret_cast<uint4*>(&s_xh[warp][128 + 4 * lane]) =
            *reinterpret_cast<uint4*>(hB);          // black
    }

    // ---- FC1 weights -> 64 registers (after gather; A/B regs are dead) ----
    uint64_t wp[4][8];
    float    b1r[4];
#pragma unroll
    for (int oo = 0; oo < 4; oo++) {
        const int o = 4 * warp + oo;
#pragma unroll
        for (int k = 0; k < 4; k++) {
            const float4 w = __ldg(&fc1w[(size_t)o * 128 + lane + 32 * k]);
            wp[oo][2 * k]     = pack_f32x2(w.x, w.y);
            wp[oo][2 * k + 1] = pack_f32x2(w.z, w.w);
        }
        b1r[oo] = __ldg(&fc1b[o]);
    }
    __syncthreads();

    // ---- FC1: warp computes its 4 outputs for all 8 positions ----
#pragma unroll
    for (int pos = 0; pos < P; pos++) {
        uint64_t xp[8];
#pragma unroll
        for (int k = 0; k < 4; k++) {
            const uint2 v = *reinterpret_cast<const uint2*>(
                &s_xh[pos][2 * (lane + 32 * k)]);
            const __half2 lo = *reinterpret_cast<const __half2*>(&v.x);
            const __half2 hi = *reinterpret_cast<const __half2*>(&v.y);
            xp[2 * k]     = h2_to_f32x2(lo);
            xp[2 * k + 1] = h2_to_f32x2(hi);
        }
        float part[4];
#pragma unroll
        for (int oo = 0; oo < 4; oo++) {
            uint64_t acc = 0ull;
#pragma unroll
            for (int k = 0; k < 8; k++)
                fma_f32x2(acc, wp[oo][k], xp[k]);
            const float2 f = unpack_f32x2(acc);
            part[oo] = f.x + f.y;
        }
#pragma unroll
        for (int off = 16; off > 0; off >>= 1) {
#pragma unroll
            for (int oo = 0; oo < 4; oo++)
                part[oo] += __shfl_xor_sync(0xffffffffu, part[oo], off);
        }
        if (lane == 0) {
#pragma unroll
            for (int oo = 0; oo < 4; oo++)
                s_h1[pos][4 * warp + oo] = fmaxf(part[oo] + b1r[oo], 0.f);
        }
    }
    __syncthreads();

    // ---- FC2 (32->32, relu) + FC3 (32->1): warp w handles position w ----
    {
        const float* h = s_h1[warp];
        float s = __ldg(&fc2b[lane]);
        const float4* w2 = fc2w + (size_t)lane * 8;
#pragma unroll
        for (int k = 0; k < 8; k++) {
            const float4 w = __ldg(&w2[k]);
            s += w.x * h[4 * k + 0];
            s += w.y * h[4 * k + 1];
            s += w.z * h[4 * k + 2];
            s += w.w * h[4 * k + 3];
        }
        float v = fmaxf(s, 0.f) * __ldg(&fc3w[lane]);
#pragma unroll
        for (int off = 16; off > 0; off >>= 1)
            v += __shfl_xor_sync(0xffffffffu, v, off);
        if (lane == 0)
            out[p0 + warp] = v + __ldg(&fc3b[0]);
    }
}

extern "C" void kernel_launch(void* const* d_in, const int* in_sizes, int n_in,
                              void* d_out, int out_size)
{
    const int*    wiP   = (const int*)d_in[0];
    const int*    biP   = (const int*)d_in[2];
    const float4* ftw   = (const float4*)d_in[4];
    const float4* ftb   = (const float4*)d_in[5];
    const float4* fc1w  = (const float4*)d_in[6];
    const float*  fc1b  = (const float*)d_in[7];
    const float4* fc2w  = (const float4*)d_in[8];
    const float*  fc2b  = (const float*)d_in[9];
    const float*  fc3w  = (const float*)d_in[10];
    const float*  fc3b  = (const float*)d_in[11];
    float* outP = (float*)d_out;

    const int n_cvt = 2 * TBL_U4;
    cvt_kernel<<<(n_cvt + 255) / 256, 256>>>(ftw, ftb);
    nnue_kernel<<<GRID, NT>>>(wiP, biP, fc1w, fc1b,
                              fc2w, fc2b, fc3w, fc3b, outP);
}